// round 2
// baseline (speedup 1.0000x reference)
#include <cuda_runtime.h>
#include <cuda_bf16.h>
#include <math.h>

// ---------------------------------------------------------------------------
// SCM: out = PWL( eps @ inv(I - A) )
//   eps: [B,16] f32, A: [16,16] f32, p: [16,101] f32, b: [16] f32
//   PWL per dim d: idx = searchsorted_right(points, z); spi = max(idx-1,0)
//                  out = (z - points[spi]) * (exp(p[d,idx])+1e-3) + delta_bias[d,spi]
// ---------------------------------------------------------------------------

#define NP1 101               // N+1 table entries
#define DIMS 16
#define VMIN_F (-5.0f)
#define INT_LEN_F (10.0f / 99.0f)
#define INV_INT_LEN_F (99.0f / 10.0f)

__device__ float  g_M[DIMS * DIMS];        // inv(I - A), row-major: z[j] = sum_k e[k]*M[k*16+j]
__device__ float2 g_wdb[DIMS * NP1];       // per (dim, idx): {w, delta_bias[max(idx-1,0)]}
__constant__ float c_M[DIMS * DIMS];

// ---------------------------------------------------------------------------
// Prep kernel: 16x16 Gauss-Jordan inverse (double, partial pivoting) + PWL tables
// Single block, 256 threads.
// ---------------------------------------------------------------------------
__global__ void prep_kernel(const float* __restrict__ A,
                            const float* __restrict__ p,
                            const float* __restrict__ b) {
    __shared__ double aug[16][33];   // [16 x 32] augmented, padded
    __shared__ double fac[16];
    __shared__ double s_scale;
    __shared__ int s_piv;

    const int tid = threadIdx.x;

    // Build [I - A | I]
    if (tid < 256) {
        int r = tid >> 4, c = tid & 15;
        aug[r][c]      = (r == c ? 1.0 : 0.0) - (double)A[r * 16 + c];
        aug[r][16 + c] = (r == c ? 1.0 : 0.0);
    }
    __syncthreads();

    for (int col = 0; col < 16; ++col) {
        if (tid == 0) {
            int piv = col;
            double best = fabs(aug[col][col]);
            for (int r = col + 1; r < 16; ++r) {
                double v = fabs(aug[r][col]);
                if (v > best) { best = v; piv = r; }
            }
            s_piv = piv;
        }
        __syncthreads();
        const int piv = s_piv;
        if (piv != col && tid < 32) {
            double t = aug[col][tid];
            aug[col][tid] = aug[piv][tid];
            aug[piv][tid] = t;
        }
        __syncthreads();
        if (tid == 0) s_scale = 1.0 / aug[col][col];
        __syncthreads();
        if (tid < 32) aug[col][tid] *= s_scale;
        __syncthreads();
        if (tid < 16) fac[tid] = aug[tid][col];
        __syncthreads();
        for (int idx = tid; idx < 512; idx += 256) {
            int r = idx >> 5, j = idx & 31;
            if (r != col) aug[r][j] -= fac[r] * aug[col][j];
        }
        __syncthreads();
    }

    if (tid < 256) {
        int r = tid >> 4, c = tid & 15;
        g_M[r * 16 + c] = (float)aug[r][16 + c];
    }

    // PWL tables: one thread per dim (serial cumsum of 99 delta_h values)
    if (tid < DIMS) {
        const int d = tid;
        const float* pd = p + d * NP1;
        float db = b[d];
        float w0 = expf(pd[0]) + 0.001f;
        g_wdb[d * NP1 + 0] = make_float2(w0, db);     // idx=0 -> spi=0 -> delta_bias[0]=b
        float prev_w = expf(pd[1]) + 0.001f;
        g_wdb[d * NP1 + 1] = make_float2(prev_w, db); // idx=1 -> spi=0 -> b
        for (int t = 2; t <= 100; ++t) {
            db += INT_LEN_F * prev_w;                 // += delta_h[t-2] = INT_LEN*(exp(p[t-1])+1e-3)
            float wt = expf(pd[t]) + 0.001f;
            g_wdb[d * NP1 + t] = make_float2(wt, db);
            prev_w = wt;
        }
    }
}

// ---------------------------------------------------------------------------
// Main kernel: one thread per row. GEMV vs constant-memory M (uniform LDCU path),
// then fused PWL lookup from a shared float2 table.
// ---------------------------------------------------------------------------
__global__ void __launch_bounds__(256) scm_main_kernel(const float4* __restrict__ eps,
                                                       float4* __restrict__ out,
                                                       int B) {
    __shared__ float2 s_wdb[DIMS * NP1];
    for (int i = threadIdx.x; i < DIMS * NP1; i += 256) s_wdb[i] = g_wdb[i];
    __syncthreads();

    const int row = blockIdx.x * 256 + threadIdx.x;
    if (row >= B) return;

    const float4* ep = eps + (size_t)row * 4;
    float4 e0 = ep[0], e1 = ep[1], e2 = ep[2], e3 = ep[3];

    float e[16] = {e0.x, e0.y, e0.z, e0.w,
                   e1.x, e1.y, e1.z, e1.w,
                   e2.x, e2.y, e2.z, e2.w,
                   e3.x, e3.y, e3.z, e3.w};
    float z[16];
#pragma unroll
    for (int j = 0; j < 16; ++j) z[j] = 0.0f;

#pragma unroll
    for (int k = 0; k < 16; ++k) {
        const float ek = e[k];
#pragma unroll
        for (int j = 0; j < 16; ++j) {
            z[j] = fmaf(ek, c_M[k * 16 + j], z[j]);
        }
    }

    float o[16];
#pragma unroll
    for (int j = 0; j < 16; ++j) {
        const float zv = z[j];
        int idx = (int)floorf((zv - VMIN_F) * INV_INT_LEN_F) + 1;
        idx = max(0, min(idx, 100));
        const int spi = max(idx - 1, 0);
        const float2 wdb = s_wdb[j * NP1 + idx];
        const float sp = fmaf((float)spi, INT_LEN_F, VMIN_F);
        o[j] = fmaf(zv - sp, wdb.x, wdb.y);
    }

    float4* op = out + (size_t)row * 4;
    op[0] = make_float4(o[0],  o[1],  o[2],  o[3]);
    op[1] = make_float4(o[4],  o[5],  o[6],  o[7]);
    op[2] = make_float4(o[8],  o[9],  o[10], o[11]);
    op[3] = make_float4(o[12], o[13], o[14], o[15]);
}

// ---------------------------------------------------------------------------
extern "C" void kernel_launch(void* const* d_in, const int* in_sizes, int n_in,
                              void* d_out, int out_size) {
    // Identify inputs by element count (robust to ordering):
    //   eps: B*16 (large), A: 256, p: 16*101=1616, b: 16
    const float* eps = nullptr;
    const float* A   = nullptr;
    const float* p   = nullptr;
    const float* b   = nullptr;
    int eps_elems = 0;
    for (int i = 0; i < n_in; ++i) {
        const int sz = in_sizes[i];
        if (sz == 256)       A = (const float*)d_in[i];
        else if (sz == 1616) p = (const float*)d_in[i];
        else if (sz == 16)   b = (const float*)d_in[i];
        else { eps = (const float*)d_in[i]; eps_elems = sz; }
    }
    const int B = eps_elems / 16;

    prep_kernel<<<1, 256>>>(A, p, b);

    void* gM_ptr = nullptr;
    cudaGetSymbolAddress(&gM_ptr, g_M);
    cudaMemcpyToSymbolAsync(c_M, gM_ptr, DIMS * DIMS * sizeof(float), 0,
                            cudaMemcpyDeviceToDevice);

    const int blocks = (B + 255) / 256;
    scm_main_kernel<<<blocks, 256>>>((const float4*)eps, (float4*)d_out, B);
}

// round 3
// speedup vs baseline: 1.4207x; 1.4207x over previous
#include <cuda_runtime.h>
#include <cuda_bf16.h>
#include <math.h>

// ---------------------------------------------------------------------------
// SCM: out = PWL( eps @ inv(I - A) )
//   eps: [B,16] f32, A: [16,16] f32, p: [16,101] f32, b: [16] f32
// Table per (dim, idx): {w, c} with c = delta_bias[spi] - sp*w so that
//   out = fma(z, w, c)
// ---------------------------------------------------------------------------

#define NP1 101
#define DIMS 16
#define VMIN_F (-5.0f)
#define INT_LEN_F (10.0f / 99.0f)
#define INV_INT_LEN_F (99.0f / 10.0f)

__device__ float  g_M[DIMS * DIMS];      // inv(I-A), row-major; z[j]=sum_k e[k]*M[k*16+j]
__device__ float2 g_wdb[DIMS * NP1];     // {w, c}
__constant__ float c_M[DIMS * DIMS];

// ---------------------------------------------------------------------------
// Prep: float Gauss-Jordan (warp-parallel pivot) + warp-per-dim PWL table build
// 1 block, 256 threads.
// ---------------------------------------------------------------------------
__global__ void prep_kernel(const float* __restrict__ A,
                            const float* __restrict__ p,
                            const float* __restrict__ b) {
    __shared__ float aug[16][33];
    __shared__ float fac[16];
    __shared__ int   s_piv;
    __shared__ float s_w[DIMS][104];   // w values per dim
    __shared__ float s_S[DIMS][104];   // prefix sums S(m), m=0..99

    const int tid = threadIdx.x;

    // Build [I - A | I]
    {
        int r = tid >> 4, c = tid & 15;
        aug[r][c]      = (r == c ? 1.0f : 0.0f) - A[r * 16 + c];
        aug[r][16 + c] = (r == c ? 1.0f : 0.0f);
    }
    __syncthreads();

    for (int col = 0; col < 16; ++col) {
        // warp-parallel pivot argmax (warp 0)
        if (tid < 32) {
            float v = (tid >= col && tid < 16) ? fabsf(aug[tid][col]) : -1.0f;
            int   ix = tid;
#pragma unroll
            for (int o = 8; o > 0; o >>= 1) {
                float vo = __shfl_down_sync(0xffffffffu, v, o);
                int   io = __shfl_down_sync(0xffffffffu, ix, o);
                if (vo > v) { v = vo; ix = io; }
            }
            if (tid == 0) s_piv = ix;
        }
        __syncthreads();
        const int piv = s_piv;
        if (piv != col && tid < 32) {
            float t = aug[col][tid];
            aug[col][tid] = aug[piv][tid];
            aug[piv][tid] = t;
        }
        __syncthreads();
        if (tid < 32) {
            float pv = aug[col][col];   // all lanes read first
            __syncwarp();
            aug[col][tid] *= (1.0f / pv);
        }
        if (tid >= 32 && tid < 48) {
            int r = tid - 32;
            fac[r] = (r == col) ? 0.0f : aug[r][col];   // rows != col untouched by scaling
        }
        __syncthreads();
        // rank-1 elimination: 512 items over 256 threads
#pragma unroll
        for (int it = 0; it < 2; ++it) {
            int id = tid + it * 256;
            int r = id >> 5, j = id & 31;
            aug[r][j] -= fac[r] * aug[col][j];
        }
        __syncthreads();
    }

    {
        int r = tid >> 4, c = tid & 15;
        g_M[r * 16 + c] = aug[r][16 + c];
    }

    // ---- PWL table: one warp per dim (8 warps, 2 dims each) ----
    const int warp = tid >> 5, lane = tid & 31;
    for (int d = warp; d < DIMS; d += 8) {
        const float* pd = p + d * NP1;
        // w[t] = exp(p[t]) + 1e-3, t = 0..100
        for (int t = lane; t < NP1; t += 32)
            s_w[d][t] = expf(pd[t]) + 0.001f;
        __syncwarp();

        // delta_h[i] = INT_LEN * w[i+1], i = 0..98 ; S(m) = sum_{i<m} delta_h[i]
        // lane handles i in [4*lane, 4*lane+4)
        float pre[4];
        float loc = 0.0f;
#pragma unroll
        for (int q = 0; q < 4; ++q) {
            int i = 4 * lane + q;
            float v = (i < 99) ? (INT_LEN_F * s_w[d][i + 1]) : 0.0f;
            loc += v;
            pre[q] = loc;              // inclusive within-lane
        }
        // inclusive warp scan of lane totals -> exclusive base
        float tot = loc;
#pragma unroll
        for (int o = 1; o < 32; o <<= 1) {
            float t = __shfl_up_sync(0xffffffffu, tot, o);
            if (lane >= o) tot += t;
        }
        float excl = tot - loc;        // S(4*lane)
#pragma unroll
        for (int q = 0; q < 4; ++q) {
            int m = 4 * lane + q;
            if (m <= 99) s_S[d][m] = excl + (q == 0 ? 0.0f : pre[q - 1]);
        }
        __syncwarp();

        // table: {w, c = b + S(spi) - sp*w}, spi = max(idx-1,0), sp = vmin + spi*Δ
        const float bd = b[d];
        for (int idx = lane; idx < NP1; idx += 32) {
            int spi = idx > 0 ? idx - 1 : 0;
            float w  = s_w[d][idx];
            float sp = fmaf((float)spi, INT_LEN_F, VMIN_F);
            float db = bd + s_S[d][spi];
            g_wdb[d * NP1 + idx] = make_float2(w, fmaf(-sp, w, db));
        }
        __syncwarp();
    }
}

// ---------------------------------------------------------------------------
// Main kernel: persistent grid-stride, 1 row per thread per iteration.
// GEMV via constant memory (LDCU/UR path), PWL = 1 cvt.rmi + clamp + LDS.64 + FMA.
// ---------------------------------------------------------------------------
__global__ void __launch_bounds__(256) scm_main_kernel(const float4* __restrict__ eps,
                                                       float4* __restrict__ out,
                                                       int B, int stride) {
    __shared__ float2 s_tab[DIMS * NP1];
    for (int i = threadIdx.x; i < DIMS * NP1; i += 256) s_tab[i] = g_wdb[i];
    __syncthreads();

    for (int row = blockIdx.x * 256 + threadIdx.x; row < B; row += stride) {
        const float4* ep = eps + (size_t)row * 4;
        const float4 e0 = __ldcs(ep + 0);
        const float4 e1 = __ldcs(ep + 1);
        const float4 e2 = __ldcs(ep + 2);
        const float4 e3 = __ldcs(ep + 3);

        const float e[16] = {e0.x, e0.y, e0.z, e0.w,
                             e1.x, e1.y, e1.z, e1.w,
                             e2.x, e2.y, e2.z, e2.w,
                             e3.x, e3.y, e3.z, e3.w};
        float z[16];
#pragma unroll
        for (int j = 0; j < 16; ++j) z[j] = 0.0f;
#pragma unroll
        for (int k = 0; k < 16; ++k) {
            const float ek = e[k];
#pragma unroll
            for (int j = 0; j < 16; ++j)
                z[j] = fmaf(ek, c_M[k * 16 + j], z[j]);
        }

        float o[16];
#pragma unroll
        for (int j = 0; j < 16; ++j) {
            const float zv = z[j];
            // idx = clamp(floor((z-vmin)/Δ) + 1, 0, 100); single cvt.rmi
            int t = __float2int_rd(fmaf(zv, INV_INT_LEN_F, 49.5f));
            t = min(t, 99);
            t = max(t + 1, 0);
            const float2 wc = s_tab[j * NP1 + t];
            o[j] = fmaf(zv, wc.x, wc.y);
        }

        float4* op = out + (size_t)row * 4;
        __stcs(op + 0, make_float4(o[0],  o[1],  o[2],  o[3]));
        __stcs(op + 1, make_float4(o[4],  o[5],  o[6],  o[7]));
        __stcs(op + 2, make_float4(o[8],  o[9],  o[10], o[11]));
        __stcs(op + 3, make_float4(o[12], o[13], o[14], o[15]));
    }
}

// ---------------------------------------------------------------------------
extern "C" void kernel_launch(void* const* d_in, const int* in_sizes, int n_in,
                              void* d_out, int out_size) {
    const float* eps = nullptr;
    const float* A   = nullptr;
    const float* p   = nullptr;
    const float* b   = nullptr;
    int eps_elems = 0;
    for (int i = 0; i < n_in; ++i) {
        const int sz = in_sizes[i];
        if (sz == 256)       A = (const float*)d_in[i];
        else if (sz == 1616) p = (const float*)d_in[i];
        else if (sz == 16)   b = (const float*)d_in[i];
        else { eps = (const float*)d_in[i]; eps_elems = sz; }
    }
    const int B = eps_elems / 16;

    prep_kernel<<<1, 256>>>(A, p, b);

    void* gM_ptr = nullptr;
    cudaGetSymbolAddress(&gM_ptr, g_M);
    cudaMemcpyToSymbolAsync(c_M, gM_ptr, DIMS * DIMS * sizeof(float), 0,
                            cudaMemcpyDeviceToDevice);

    int sm_count = 148;
    cudaDeviceGetAttribute(&sm_count, cudaDevAttrMultiProcessorCount, 0);
    const int blocks = sm_count * 6;     // 40 regs/thread -> 6 blocks of 256 resident
    const int stride = blocks * 256;
    scm_main_kernel<<<blocks, 256>>>((const float4*)eps, (float4*)d_out, B, stride);
}

// round 4
// speedup vs baseline: 1.4761x; 1.0390x over previous
#include <cuda_runtime.h>
#include <cuda_bf16.h>
#include <math.h>

// ---------------------------------------------------------------------------
// SCM: out = PWL( eps @ inv(I - A) )
//   eps: [B,16] f32, A: [16,16] f32, p: [16,101] f32, b: [16] f32
// Table per (dim, idx): {w, c} with c = delta_bias[spi] - sp*w  ->  out = fma(z,w,c)
// GEMV uses packed fp32x2 FMA (FFMA2) against 64-bit constant-memory words.
// ---------------------------------------------------------------------------

#define NP1 101
#define DIMS 16
#define VMIN_F (-5.0f)
#define INT_LEN_F (10.0f / 99.0f)
#define INV_INT_LEN_F (99.0f / 10.0f)

__device__ float  g_M[DIMS * DIMS];      // inv(I-A), row-major; z[j]=sum_k e[k]*M[k*16+j]
__device__ float2 g_wdb[DIMS * NP1];     // {w, c}
__constant__ unsigned long long c_M2[DIMS * 8];   // same bytes as g_M, viewed as f32x2

// ---- f32x2 helpers --------------------------------------------------------
__device__ __forceinline__ unsigned long long ffma2(unsigned long long a,
                                                    unsigned long long b,
                                                    unsigned long long c) {
    unsigned long long d;
    asm("fma.rn.f32x2 %0, %1, %2, %3;" : "=l"(d) : "l"(a), "l"(b), "l"(c));
    return d;
}
__device__ __forceinline__ unsigned long long pack2(float x) {
    unsigned long long d;
    asm("mov.b64 %0, {%1, %1};" : "=l"(d) : "f"(x));
    return d;
}
__device__ __forceinline__ void unpack2(unsigned long long v, float& lo, float& hi) {
    asm("mov.b64 {%0, %1}, %2;" : "=f"(lo), "=f"(hi) : "l"(v));
}

// ---------------------------------------------------------------------------
// Prep: float Gauss-Jordan (warp-parallel pivot) + warp-per-dim PWL table build
// ---------------------------------------------------------------------------
__global__ void prep_kernel(const float* __restrict__ A,
                            const float* __restrict__ p,
                            const float* __restrict__ b) {
    __shared__ float aug[16][33];
    __shared__ float fac[16];
    __shared__ int   s_piv;
    __shared__ float s_w[DIMS][104];
    __shared__ float s_S[DIMS][104];

    const int tid = threadIdx.x;

    {
        int r = tid >> 4, c = tid & 15;
        aug[r][c]      = (r == c ? 1.0f : 0.0f) - A[r * 16 + c];
        aug[r][16 + c] = (r == c ? 1.0f : 0.0f);
    }
    __syncthreads();

    for (int col = 0; col < 16; ++col) {
        if (tid < 32) {
            float v = (tid >= col && tid < 16) ? fabsf(aug[tid][col]) : -1.0f;
            int   ix = tid;
#pragma unroll
            for (int o = 8; o > 0; o >>= 1) {
                float vo = __shfl_down_sync(0xffffffffu, v, o);
                int   io = __shfl_down_sync(0xffffffffu, ix, o);
                if (vo > v) { v = vo; ix = io; }
            }
            if (tid == 0) s_piv = ix;
        }
        __syncthreads();
        const int piv = s_piv;
        if (piv != col && tid < 32) {
            float t = aug[col][tid];
            aug[col][tid] = aug[piv][tid];
            aug[piv][tid] = t;
        }
        __syncthreads();
        if (tid < 32) {
            float pv = aug[col][col];
            __syncwarp();
            aug[col][tid] *= (1.0f / pv);
        }
        if (tid >= 32 && tid < 48) {
            int r = tid - 32;
            fac[r] = (r == col) ? 0.0f : aug[r][col];
        }
        __syncthreads();
#pragma unroll
        for (int it = 0; it < 2; ++it) {
            int id = tid + it * 256;
            int r = id >> 5, j = id & 31;
            aug[r][j] -= fac[r] * aug[col][j];
        }
        __syncthreads();
    }

    {
        int r = tid >> 4, c = tid & 15;
        g_M[r * 16 + c] = aug[r][16 + c];
    }

    // ---- PWL table: one warp per dim ----
    const int warp = tid >> 5, lane = tid & 31;
    for (int d = warp; d < DIMS; d += 8) {
        const float* pd = p + d * NP1;
        for (int t = lane; t < NP1; t += 32)
            s_w[d][t] = expf(pd[t]) + 0.001f;
        __syncwarp();

        float pre[4];
        float loc = 0.0f;
#pragma unroll
        for (int q = 0; q < 4; ++q) {
            int i = 4 * lane + q;
            float v = (i < 99) ? (INT_LEN_F * s_w[d][i + 1]) : 0.0f;
            loc += v;
            pre[q] = loc;
        }
        float tot = loc;
#pragma unroll
        for (int o = 1; o < 32; o <<= 1) {
            float t = __shfl_up_sync(0xffffffffu, tot, o);
            if (lane >= o) tot += t;
        }
        float excl = tot - loc;
#pragma unroll
        for (int q = 0; q < 4; ++q) {
            int m = 4 * lane + q;
            if (m <= 99) s_S[d][m] = excl + (q == 0 ? 0.0f : pre[q - 1]);
        }
        __syncwarp();

        const float bd = b[d];
        for (int idx = lane; idx < NP1; idx += 32) {
            int spi = idx > 0 ? idx - 1 : 0;
            float w  = s_w[d][idx];
            float sp = fmaf((float)spi, INT_LEN_F, VMIN_F);
            float db = bd + s_S[d][spi];
            g_wdb[d * NP1 + idx] = make_float2(w, fmaf(-sp, w, db));
        }
        __syncwarp();
    }
}

// ---------------------------------------------------------------------------
// Main kernel: persistent grid-stride, 1 row/thread/iter.
// GEMV: 128 x FFMA2 (f32x2) with LDCU.64 constant operands.
// PWL:  cvt.rmi + clamp + LDS.64 + FMA per output element.
// ---------------------------------------------------------------------------
__global__ void __launch_bounds__(256) scm_main_kernel(const float4* __restrict__ eps,
                                                       float4* __restrict__ out,
                                                       int B, int stride) {
    __shared__ float2 s_tab[DIMS * NP1];
    for (int i = threadIdx.x; i < DIMS * NP1; i += 256) s_tab[i] = g_wdb[i];
    __syncthreads();

    for (int row = blockIdx.x * 256 + threadIdx.x; row < B; row += stride) {
        const float4* ep = eps + (size_t)row * 4;
        const float4 e0 = __ldcs(ep + 0);
        const float4 e1 = __ldcs(ep + 1);
        const float4 e2 = __ldcs(ep + 2);
        const float4 e3 = __ldcs(ep + 3);

        const float e[16] = {e0.x, e0.y, e0.z, e0.w,
                             e1.x, e1.y, e1.z, e1.w,
                             e2.x, e2.y, e2.z, e2.w,
                             e3.x, e3.y, e3.z, e3.w};

        unsigned long long z2[8];
#pragma unroll
        for (int j = 0; j < 8; ++j) z2[j] = 0ULL;

#pragma unroll
        for (int k = 0; k < 16; ++k) {
            const unsigned long long ek2 = pack2(e[k]);
#pragma unroll
            for (int j = 0; j < 8; ++j)
                z2[j] = ffma2(ek2, c_M2[k * 8 + j], z2[j]);
        }

        float o[16];
#pragma unroll
        for (int j2 = 0; j2 < 8; ++j2) {
            float zlo, zhi;
            unpack2(z2[j2], zlo, zhi);
#pragma unroll
            for (int h = 0; h < 2; ++h) {
                const int j = 2 * j2 + h;
                const float zv = h ? zhi : zlo;
                int t = __float2int_rd(fmaf(zv, INV_INT_LEN_F, 49.5f));
                t = min(t, 99);
                t = max(t + 1, 0);
                const float2 wc = s_tab[j * NP1 + t];
                o[j] = fmaf(zv, wc.x, wc.y);
            }
        }

        float4* op = out + (size_t)row * 4;
        __stcs(op + 0, make_float4(o[0],  o[1],  o[2],  o[3]));
        __stcs(op + 1, make_float4(o[4],  o[5],  o[6],  o[7]));
        __stcs(op + 2, make_float4(o[8],  o[9],  o[10], o[11]));
        __stcs(op + 3, make_float4(o[12], o[13], o[14], o[15]));
    }
}

// ---------------------------------------------------------------------------
extern "C" void kernel_launch(void* const* d_in, const int* in_sizes, int n_in,
                              void* d_out, int out_size) {
    const float* eps = nullptr;
    const float* A   = nullptr;
    const float* p   = nullptr;
    const float* b   = nullptr;
    int eps_elems = 0;
    for (int i = 0; i < n_in; ++i) {
        const int sz = in_sizes[i];
        if (sz == 256)       A = (const float*)d_in[i];
        else if (sz == 1616) p = (const float*)d_in[i];
        else if (sz == 16)   b = (const float*)d_in[i];
        else { eps = (const float*)d_in[i]; eps_elems = sz; }
    }
    const int B = eps_elems / 16;

    prep_kernel<<<1, 256>>>(A, p, b);

    void* gM_ptr = nullptr;
    cudaGetSymbolAddress(&gM_ptr, g_M);
    cudaMemcpyToSymbolAsync(c_M2, gM_ptr, DIMS * DIMS * sizeof(float), 0,
                            cudaMemcpyDeviceToDevice);

    int sm_count = 148;
    cudaDeviceGetAttribute(&sm_count, cudaDevAttrMultiProcessorCount, 0);
    int blocks_per_sm = 6;
    cudaOccupancyMaxActiveBlocksPerMultiprocessor(&blocks_per_sm, scm_main_kernel,
                                                  256, DIMS * NP1 * sizeof(float2));
    if (blocks_per_sm < 1) blocks_per_sm = 1;
    const int blocks = sm_count * blocks_per_sm;
    const int stride = blocks * 256;
    scm_main_kernel<<<blocks, 256>>>((const float4*)eps, (float4*)d_out, B, stride);
}

// round 6
// speedup vs baseline: 1.5151x; 1.0264x over previous
#include <cuda_runtime.h>
#include <cuda_bf16.h>
#include <math.h>

// ---------------------------------------------------------------------------
// SCM: out = PWL( eps @ inv(I - A) )
//   eps: [B,16] f32, A: [16,16] f32, p: [16,101] f32, b: [16] f32
// Table per (dim, idx): {w, c} with c = delta_bias[spi] - sp*w  ->  out = fma(z,w,c)
// GEMV: packed fp32x2 FMA (FFMA2) vs 64-bit constant words.
// Main loop software-pipelined: next row's loads issued before current compute.
// ---------------------------------------------------------------------------

#define NP1 101
#define DIMS 16
#define VMIN_F (-5.0f)
#define INT_LEN_F (10.0f / 99.0f)
#define INV_INT_LEN_F (99.0f / 10.0f)

__device__ float  g_M[DIMS * DIMS];
__device__ float2 g_wdb[DIMS * NP1];
__constant__ unsigned long long c_M2[DIMS * 8];

__device__ __forceinline__ unsigned long long ffma2(unsigned long long a,
                                                    unsigned long long b,
                                                    unsigned long long c) {
    unsigned long long d;
    asm("fma.rn.f32x2 %0, %1, %2, %3;" : "=l"(d) : "l"(a), "l"(b), "l"(c));
    return d;
}
__device__ __forceinline__ unsigned long long pack2(float x) {
    unsigned long long d;
    asm("mov.b64 %0, {%1, %1};" : "=l"(d) : "f"(x));
    return d;
}
__device__ __forceinline__ void unpack2(unsigned long long v, float& lo, float& hi) {
    asm("mov.b64 {%0, %1}, %2;" : "=f"(lo), "=f"(hi) : "l"(v));
}

// ---------------------------------------------------------------------------
// Prep: float Gauss-Jordan (warp-parallel pivot) + warp-per-dim PWL tables
// ---------------------------------------------------------------------------
__global__ void prep_kernel(const float* __restrict__ A,
                            const float* __restrict__ p,
                            const float* __restrict__ b) {
    __shared__ float aug[16][33];
    __shared__ float fac[16];
    __shared__ int   s_piv;
    __shared__ float s_w[DIMS][104];
    __shared__ float s_S[DIMS][104];

    const int tid = threadIdx.x;

    {
        int r = tid >> 4, c = tid & 15;
        aug[r][c]      = (r == c ? 1.0f : 0.0f) - A[r * 16 + c];
        aug[r][16 + c] = (r == c ? 1.0f : 0.0f);
    }
    __syncthreads();

    for (int col = 0; col < 16; ++col) {
        if (tid < 32) {
            float v = (tid >= col && tid < 16) ? fabsf(aug[tid][col]) : -1.0f;
            int   ix = tid;
#pragma unroll
            for (int o = 8; o > 0; o >>= 1) {
                float vo = __shfl_down_sync(0xffffffffu, v, o);
                int   io = __shfl_down_sync(0xffffffffu, ix, o);
                if (vo > v) { v = vo; ix = io; }
            }
            if (tid == 0) s_piv = ix;
        }
        __syncthreads();
        const int piv = s_piv;
        if (piv != col && tid < 32) {
            float t = aug[col][tid];
            aug[col][tid] = aug[piv][tid];
            aug[piv][tid] = t;
        }
        __syncthreads();
        if (tid < 32) {
            float pv = aug[col][col];
            __syncwarp();
            aug[col][tid] *= (1.0f / pv);
        }
        if (tid >= 32 && tid < 48) {
            int r = tid - 32;
            fac[r] = (r == col) ? 0.0f : aug[r][col];
        }
        __syncthreads();
#pragma unroll
        for (int it = 0; it < 2; ++it) {
            int id = tid + it * 256;
            int r = id >> 5, j = id & 31;
            aug[r][j] -= fac[r] * aug[col][j];
        }
        __syncthreads();
    }

    {
        int r = tid >> 4, c = tid & 15;
        g_M[r * 16 + c] = aug[r][16 + c];
    }

    const int warp = tid >> 5, lane = tid & 31;
    for (int d = warp; d < DIMS; d += 8) {
        const float* pd = p + d * NP1;
        for (int t = lane; t < NP1; t += 32)
            s_w[d][t] = expf(pd[t]) + 0.001f;
        __syncwarp();

        float pre[4];
        float loc = 0.0f;
#pragma unroll
        for (int q = 0; q < 4; ++q) {
            int i = 4 * lane + q;
            float v = (i < 99) ? (INT_LEN_F * s_w[d][i + 1]) : 0.0f;
            loc += v;
            pre[q] = loc;
        }
        float tot = loc;
#pragma unroll
        for (int o = 1; o < 32; o <<= 1) {
            float t = __shfl_up_sync(0xffffffffu, tot, o);
            if (lane >= o) tot += t;
        }
        float excl = tot - loc;
#pragma unroll
        for (int q = 0; q < 4; ++q) {
            int m = 4 * lane + q;
            if (m <= 99) s_S[d][m] = excl + (q == 0 ? 0.0f : pre[q - 1]);
        }
        __syncwarp();

        const float bd = b[d];
        for (int idx = lane; idx < NP1; idx += 32) {
            int spi = idx > 0 ? idx - 1 : 0;
            float w  = s_w[d][idx];
            float sp = fmaf((float)spi, INT_LEN_F, VMIN_F);
            float db = bd + s_S[d][spi];
            g_wdb[d * NP1 + idx] = make_float2(w, fmaf(-sp, w, db));
        }
        __syncwarp();
    }
}

// ---------------------------------------------------------------------------
// Main kernel: persistent grid-stride, software-pipelined (prefetch next row).
// ---------------------------------------------------------------------------
__global__ void __launch_bounds__(256) scm_main_kernel(const float4* __restrict__ eps,
                                                       float4* __restrict__ out,
                                                       int B, int stride) {
    __shared__ float2 s_tab[DIMS * NP1];
    for (int i = threadIdx.x; i < DIMS * NP1; i += 256) s_tab[i] = g_wdb[i];
    __syncthreads();

    int row = blockIdx.x * 256 + threadIdx.x;
    if (row >= B) return;

    // prologue load
    const float4* ep = eps + (size_t)row * 4;
    float4 n0 = __ldcs(ep + 0);
    float4 n1 = __ldcs(ep + 1);
    float4 n2 = __ldcs(ep + 2);
    float4 n3 = __ldcs(ep + 3);

    while (true) {
        const float4 e0 = n0, e1 = n1, e2 = n2, e3 = n3;
        const int next = row + stride;

        // prefetch next row before touching current data
        if (next < B) {
            const float4* np = eps + (size_t)next * 4;
            n0 = __ldcs(np + 0);
            n1 = __ldcs(np + 1);
            n2 = __ldcs(np + 2);
            n3 = __ldcs(np + 3);
        }

        const float e[16] = {e0.x, e0.y, e0.z, e0.w,
                             e1.x, e1.y, e1.z, e1.w,
                             e2.x, e2.y, e2.z, e2.w,
                             e3.x, e3.y, e3.z, e3.w};

        unsigned long long z2[8];
#pragma unroll
        for (int j = 0; j < 8; ++j) z2[j] = 0ULL;

#pragma unroll
        for (int k = 0; k < 16; ++k) {
            const unsigned long long ek2 = pack2(e[k]);
#pragma unroll
            for (int j = 0; j < 8; ++j)
                z2[j] = ffma2(ek2, c_M2[k * 8 + j], z2[j]);
        }

        float o[16];
#pragma unroll
        for (int j2 = 0; j2 < 8; ++j2) {
            float zlo, zhi;
            unpack2(z2[j2], zlo, zhi);
#pragma unroll
            for (int h = 0; h < 2; ++h) {
                const int j = 2 * j2 + h;
                const float zv = h ? zhi : zlo;
                int t = __float2int_rd(fmaf(zv, INV_INT_LEN_F, 49.5f));
                t = min(t, 99);
                t = max(t + 1, 0);
                const float2 wc = s_tab[j * NP1 + t];
                o[j] = fmaf(zv, wc.x, wc.y);
            }
        }

        float4* op = out + (size_t)row * 4;
        __stcs(op + 0, make_float4(o[0],  o[1],  o[2],  o[3]));
        __stcs(op + 1, make_float4(o[4],  o[5],  o[6],  o[7]));
        __stcs(op + 2, make_float4(o[8],  o[9],  o[10], o[11]));
        __stcs(op + 3, make_float4(o[12], o[13], o[14], o[15]));

        if (next >= B) break;
        row = next;
    }
}

// ---------------------------------------------------------------------------
extern "C" void kernel_launch(void* const* d_in, const int* in_sizes, int n_in,
                              void* d_out, int out_size) {
    const float* eps = nullptr;
    const float* A   = nullptr;
    const float* p   = nullptr;
    const float* b   = nullptr;
    int eps_elems = 0;
    for (int i = 0; i < n_in; ++i) {
        const int sz = in_sizes[i];
        if (sz == 256)       A = (const float*)d_in[i];
        else if (sz == 1616) p = (const float*)d_in[i];
        else if (sz == 16)   b = (const float*)d_in[i];
        else { eps = (const float*)d_in[i]; eps_elems = sz; }
    }
    const int B = eps_elems / 16;

    prep_kernel<<<1, 256>>>(A, p, b);

    void* gM_ptr = nullptr;
    cudaGetSymbolAddress(&gM_ptr, g_M);
    cudaMemcpyToSymbolAsync(c_M2, gM_ptr, DIMS * DIMS * sizeof(float), 0,
                            cudaMemcpyDeviceToDevice);

    int sm_count = 148;
    cudaDeviceGetAttribute(&sm_count, cudaDevAttrMultiProcessorCount, 0);
    int blocks_per_sm = 6;
    cudaOccupancyMaxActiveBlocksPerMultiprocessor(&blocks_per_sm, scm_main_kernel,
                                                  256, DIMS * NP1 * sizeof(float2));
    if (blocks_per_sm < 1) blocks_per_sm = 1;
    const int blocks = sm_count * blocks_per_sm;
    const int stride = blocks * 256;
    scm_main_kernel<<<blocks, 256>>>((const float4*)eps, (float4*)d_out, B, stride);
}